// round 7
// baseline (speedup 1.0000x reference)
#include <cuda_runtime.h>
#include <cuda_bf16.h>
#include <cstdint>

// ForceGrid: NGP deposit of 10M weighted particles into a 256^3 float grid.
// fi5 = RN(RN(RN(x+10) * 12.75f) + 0.5f)  (replicates XLA's reciprocal-mul,
// three separately-rounded ops), index = trunc(fi5), in-bounds -> red.add.
// R7: keep the L2 evict_last pin (R6 win), drop the register double-buffer
// (regs 44 -> ~30, occ 57% -> ~80%) so more eligible warps feed the REDG
// dispatch pipe; 4 particles/iter keeps MLP_p1=4 (avoids L1tex-queue spread).

#define GRID_N 256

__device__ __forceinline__ uint64_t make_evict_last_policy() {
    uint64_t pol;
    asm volatile("createpolicy.fractional.L2::evict_last.b64 %0, 1.0;" : "=l"(pol));
    return pol;
}

__device__ __forceinline__ void deposit_one(float x, float y, float z, float w,
                                            float* __restrict__ grid,
                                            uint64_t pol) {
    const float R = 12.75f;  // RN(1 / RN(20/255)) == 12.75 exactly
    float fx = __fadd_rn(__fmul_rn(__fadd_rn(x, 10.0f), R), 0.5f);
    float fy = __fadd_rn(__fmul_rn(__fadd_rn(y, 10.0f), R), 0.5f);
    float fz = __fadd_rn(__fmul_rn(__fadd_rn(z, 10.0f), R), 0.5f);
    int ix = (int)fx;   // trunc toward zero == astype(int32)
    int iy = (int)fy;
    int iz = (int)fz;
    if (((unsigned)ix < GRID_N) & ((unsigned)iy < GRID_N) & ((unsigned)iz < GRID_N)) {
        int flat = (ix * GRID_N + iy) * GRID_N + iz;
        // Reduction with L2 evict_last cache hint: keeps grid lines resident.
        asm volatile("red.global.L2::cache_hint.add.f32 [%0], %1, %2;"
                     :: "l"(grid + flat), "f"(w), "l"(pol) : "memory");
    }
}

// Zero the grid with evict_last-policy stores: lines enter L2 dirty + pinned.
__global__ void __launch_bounds__(256)
forcegrid_zero_kernel(float4* __restrict__ grid4, int n4) {
    int i = blockIdx.x * blockDim.x + threadIdx.x;
    int stride = gridDim.x * blockDim.x;
    const float z = 0.0f;
    const uint64_t pol = make_evict_last_policy();
    for (; i < n4; i += stride) {
        asm volatile("st.global.L2::cache_hint.v4.f32 [%0], {%1, %2, %3, %4}, %5;"
                     :: "l"(grid4 + i), "f"(z), "f"(z), "f"(z), "f"(z), "l"(pol)
                     : "memory");
    }
}

__global__ void __launch_bounds__(256)
forcegrid_deposit_kernel(const float4* __restrict__ pos4,
                         const float4* __restrict__ w4,
                         const float*  __restrict__ pos_scalar,
                         const float*  __restrict__ w_scalar,
                         float* __restrict__ grid,
                         int n_particles) {
    const int nq = n_particles >> 2;                 // full quads
    const int stride = gridDim.x * blockDim.x;
    const uint64_t pol = make_evict_last_policy();

    for (int q = blockIdx.x * blockDim.x + threadIdx.x; q < nq; q += stride) {
        // 3 coalesced float4 loads cover 4 particles' xyz; 1 float4 = 4 weights.
        float4 a = __ldcs(&pos4[3 * q + 0]);
        float4 b = __ldcs(&pos4[3 * q + 1]);
        float4 c = __ldcs(&pos4[3 * q + 2]);
        float4 w = __ldcs(&w4[q]);
        deposit_one(a.x, a.y, a.z, w.x, grid, pol);
        deposit_one(a.w, b.x, b.y, w.y, grid, pol);
        deposit_one(b.z, b.w, c.x, w.z, grid, pol);
        deposit_one(c.y, c.z, c.w, w.w, grid, pol);
    }

    // tail (n_particles % 4 != 0) — single thread, scalar path
    if (blockIdx.x == 0 && threadIdx.x == 0) {
        for (int p = nq * 4; p < n_particles; p++) {
            deposit_one(pos_scalar[3 * p + 0], pos_scalar[3 * p + 1],
                        pos_scalar[3 * p + 2], w_scalar[p], grid, pol);
        }
    }
}

extern "C" void kernel_launch(void* const* d_in, const int* in_sizes, int n_in,
                              void* d_out, int out_size) {
    const float* positions = (const float*)d_in[0];   // [N,3] f32
    const float* weights   = (const float*)d_in[1];   // [N]   f32
    float* grid = (float*)d_out;                      // 256^3 f32

    int n_particles = in_sizes[1];                    // N from weights

    int threads = 256;

    // Zero + L2-pin the grid (out_size is 256^3, divisible by 4).
    int n4 = out_size / 4;
    int zblocks = 148 * 8;
    forcegrid_zero_kernel<<<zblocks, threads, 0, 0>>>((float4*)d_out, n4);

    // Persistent deposit, grid-stride, 4 particles per iteration.
    int blocks = 148 * 16;
    forcegrid_deposit_kernel<<<blocks, threads, 0, 0>>>(
        (const float4*)positions, (const float4*)weights,
        positions, weights, grid, n_particles);
}